// round 3
// baseline (speedup 1.0000x reference)
#include <cuda_runtime.h>

// MatchNet: per-row MLP(6->20->20->20->8, tanh) + 150-iter PDHG LP.
// R3: 2 rows per thread (two independent dependence chains per warp to fill
// latency stalls), tree reduction for the prox norm, vectorized I/O.

#define NTHREADS 32
#define RPT 2              // rows per thread

__device__ __forceinline__ float fast_rsqrt(float v) {
    float r;
    asm("rsqrt.approx.f32 %0, %1;" : "=f"(r) : "f"(v));
    return r;
}

__device__ __forceinline__ float fast_tanh(float x) {
    float e = __expf(2.0f * x);
    return 1.0f - __fdividef(2.0f, e + 1.0f);
}

__global__ __launch_bounds__(NTHREADS)
void matchnet_kernel(
    const float* __restrict__ X,
    const float* __restrict__ W1, const float* __restrict__ b1,
    const float* __restrict__ W2, const float* __restrict__ b2,
    const float* __restrict__ W3, const float* __restrict__ b3,
    const float* __restrict__ W4, const float* __restrict__ b4,
    float* __restrict__ out, int B)
{
    __shared__ float sW1[120], sW2[400], sW3[400], sW4[160];
    __shared__ float sb1[20], sb2[20], sb3[20], sb4[8];

    const int t = threadIdx.x;
    for (int i = t; i < 120; i += NTHREADS) sW1[i] = W1[i];
    for (int i = t; i < 400; i += NTHREADS) sW2[i] = W2[i];
    for (int i = t; i < 400; i += NTHREADS) sW3[i] = W3[i];
    for (int i = t; i < 160; i += NTHREADS) sW4[i] = W4[i];
    if (t < 20) { sb1[t] = b1[t]; sb2[t] = b2[t]; sb3[t] = b3[t]; }
    if (t < 8)  { sb4[t] = b4[t]; }
    __syncthreads();

    // rows handled: blockBase + t + 32*r  (coalesced across warp)
    const int base = blockIdx.x * (NTHREADS * RPT) + t;
    int rows[RPT];
#pragma unroll
    for (int r = 0; r < RPT; r++) rows[r] = base + NTHREADS * r;

    // ---- load input rows (also the RHS b of the LP); float2-vectorized ----
    float Z[RPT][6];
#pragma unroll
    for (int r = 0; r < RPT; r++) {
        const float2* p = (const float2*)(X + rows[r] * 6);
        float2 a0 = p[0], a1 = p[1], a2 = p[2];
        Z[r][0] = a0.x; Z[r][1] = a0.y;
        Z[r][2] = a1.x; Z[r][3] = a1.y;
        Z[r][4] = a2.x; Z[r][5] = a2.y;
    }

    // ---- MLP (both rows interleaved for ILP) ----
    float h1[RPT][20], h2[RPT][20];
#pragma unroll
    for (int j = 0; j < 20; j++) {
        float s[RPT];
#pragma unroll
        for (int r = 0; r < RPT; r++) s[r] = sb1[j];
#pragma unroll
        for (int k = 0; k < 6; k++) {
            float w = sW1[k * 20 + j];
#pragma unroll
            for (int r = 0; r < RPT; r++) s[r] = fmaf(Z[r][k], w, s[r]);
        }
#pragma unroll
        for (int r = 0; r < RPT; r++) h1[r][j] = fast_tanh(s[r]);
    }
#pragma unroll
    for (int j = 0; j < 20; j++) {
        float s[RPT];
#pragma unroll
        for (int r = 0; r < RPT; r++) s[r] = sb2[j];
#pragma unroll
        for (int k = 0; k < 20; k++) {
            float w = sW2[k * 20 + j];
#pragma unroll
            for (int r = 0; r < RPT; r++) s[r] = fmaf(h1[r][k], w, s[r]);
        }
#pragma unroll
        for (int r = 0; r < RPT; r++) h2[r][j] = fast_tanh(s[r]);
    }
#pragma unroll
    for (int j = 0; j < 20; j++) {
        float s[RPT];
#pragma unroll
        for (int r = 0; r < RPT; r++) s[r] = sb3[j];
#pragma unroll
        for (int k = 0; k < 20; k++) {
            float w = sW3[k * 20 + j];
#pragma unroll
            for (int r = 0; r < RPT; r++) s[r] = fmaf(h2[r][k], w, s[r]);
        }
#pragma unroll
        for (int r = 0; r < RPT; r++) h1[r][j] = fast_tanh(s[r]); // reuse as h3
    }
    float z[RPT][8];
#pragma unroll
    for (int j = 0; j < 8; j++) {
        float s[RPT];
#pragma unroll
        for (int r = 0; r < RPT; r++) s[r] = sb4[j];
#pragma unroll
        for (int k = 0; k < 20; k++) {
            float w = sW4[k * 8 + j];
#pragma unroll
            for (int r = 0; r < RPT; r++) s[r] = fmaf(h1[r][k], w, s[r]);
        }
#pragma unroll
        for (int r = 0; r < RPT; r++) z[r][j] = s[r];
    }

    // ---- PDHG ----
    const float tau   = 0.18898223650461357f;  // 1/sqrt(28)
    const float sigma = tau;
    const float tc    = tau * 10.0f;

    float x[RPT][8], xb[RPT][8], sd[RPT][8], yI[RPT][8], y6[RPT][6];
#pragma unroll
    for (int r = 0; r < RPT; r++) {
#pragma unroll
        for (int j = 0; j < 8; j++) {
            x[r][j]  = fmaxf(z[r][j], 0.0f);
            xb[r][j] = x[r][j];
            sd[r][j] = x[r][j] - z[r][j];
            yI[r][j] = 0.0f;
        }
#pragma unroll
        for (int i = 0; i < 6; i++) y6[r][i] = 0.0f;
    }

#pragma unroll 1
    for (int it = 0; it < 150; it++) {
#pragma unroll
        for (int r = 0; r < RPT; r++) {
            // s = S @ xbar (hardcoded 0/1 pattern)
            float s0 = (xb[r][0] + xb[r][2]) + (xb[r][5] + xb[r][7]);
            float s1 = (xb[r][1] + xb[r][3]) + xb[r][4];
            float s2 = (xb[r][0] + xb[r][1]) + xb[r][6];
            float s3 = (xb[r][2] + xb[r][3]) + xb[r][5];
            float s4 = (xb[r][1] + xb[r][2]) + (xb[r][4] + xb[r][7]);
            float s5 = (xb[r][0] + xb[r][4]) + xb[r][6];

            // dual ascent + proj >= 0
            y6[r][0] = fmaxf(0.0f, fmaf(sigma, s0 - Z[r][0], y6[r][0]));
            y6[r][1] = fmaxf(0.0f, fmaf(sigma, s1 - Z[r][1], y6[r][1]));
            y6[r][2] = fmaxf(0.0f, fmaf(sigma, s2 - Z[r][2], y6[r][2]));
            y6[r][3] = fmaxf(0.0f, fmaf(sigma, s3 - Z[r][3], y6[r][3]));
            y6[r][4] = fmaxf(0.0f, fmaf(sigma, s4 - Z[r][4], y6[r][4]));
            y6[r][5] = fmaxf(0.0f, fmaf(sigma, s5 - Z[r][5], y6[r][5]));
#pragma unroll
            for (int j = 0; j < 8; j++)
                yI[r][j] = fmaxf(0.0f, fmaf(-sigma, xb[r][j], yI[r][j]));

            // g = S^T y6 - yI
            float g[8];
            g[0] = (y6[r][0] + y6[r][2]) + (y6[r][5] - yI[r][0]);
            g[1] = (y6[r][1] + y6[r][2]) + (y6[r][4] - yI[r][1]);
            g[2] = (y6[r][0] + y6[r][3]) + (y6[r][4] - yI[r][2]);
            g[3] = (y6[r][1] + y6[r][3]) - yI[r][3];
            g[4] = (y6[r][1] + y6[r][4]) + (y6[r][5] - yI[r][4]);
            g[5] = (y6[r][0] + y6[r][3]) - yI[r][5];
            g[6] = (y6[r][2] + y6[r][5]) - yI[r][6];
            g[7] = (y6[r][0] + y6[r][4]) - yI[r][7];

            // prox: d = fma(-tau, g, sd + tau); nn = ||d||^2 (tree)
            float d[8];
#pragma unroll
            for (int j = 0; j < 8; j++)
                d[j] = fmaf(-tau, g[j], sd[r][j] + tau);
            float p0 = fmaf(d[0], d[0], d[1] * d[1]);
            float p1 = fmaf(d[2], d[2], d[3] * d[3]);
            float p2 = fmaf(d[4], d[4], d[5] * d[5]);
            float p3 = fmaf(d[6], d[6], d[7] * d[7]);
            float nn = (p0 + p1) + (p2 + p3);

            float rr = fast_rsqrt(fmaxf(nn, 1e-24f));
            float scale = fmaxf(0.0f, fmaf(-tc, rr, 1.0f));
#pragma unroll
            for (int j = 0; j < 8; j++) {
                float sdn = scale * d[j];
                float xn  = z[r][j] + sdn;
                xb[r][j] = fmaf(2.0f, xn, -x[r][j]);
                x[r][j]  = xn;
                sd[r][j] = sdn;
            }
        }
    }

    // ---- store (float4-vectorized, coalesced) ----
#pragma unroll
    for (int r = 0; r < RPT; r++) {
        float4* p = (float4*)(out + rows[r] * 8);
        p[0] = make_float4(x[r][0], x[r][1], x[r][2], x[r][3]);
        p[1] = make_float4(x[r][4], x[r][5], x[r][6], x[r][7]);
    }
}

extern "C" void kernel_launch(void* const* d_in, const int* in_sizes, int n_in,
                              void* d_out, int out_size) {
    const float* X  = (const float*)d_in[0];
    const float* W1 = (const float*)d_in[1];
    const float* b1 = (const float*)d_in[2];
    const float* W2 = (const float*)d_in[3];
    const float* b2 = (const float*)d_in[4];
    const float* W3 = (const float*)d_in[5];
    const float* b3 = (const float*)d_in[6];
    const float* W4 = (const float*)d_in[7];
    const float* b4 = (const float*)d_in[8];

    const int B = in_sizes[0] / 6;
    const int rowsPerBlock = NTHREADS * RPT;
    const int grid = (B + rowsPerBlock - 1) / rowsPerBlock;
    matchnet_kernel<<<grid, NTHREADS>>>(X, W1, b1, W2, b2, W3, b3, W4, b4,
                                        (float*)d_out, B);
}

// round 4
// speedup vs baseline: 1.1437x; 1.1437x over previous
#include <cuda_runtime.h>

// MatchNet: per-row MLP(6->20->20->20->8, tanh) + 150-iter PDHG LP.
// R4: 1 row/thread (1024 warps), PDHG restructured so the S-gather and the
// pre-scale halves of both dual updates execute in the rsqrt latency shadow.
// State: sdt = (x - z) + tau, Ssd = S(x - z), y6, yI.

#define NTHREADS 32

__device__ __forceinline__ float fast_rsqrt(float v) {
    float r;
    asm("rsqrt.approx.f32 %0, %1;" : "=f"(r) : "f"(v));
    return r;
}

__device__ __forceinline__ float fast_tanh(float x) {
    float e = __expf(2.0f * x);
    return 1.0f - __fdividef(2.0f, e + 1.0f);
}

__global__ __launch_bounds__(NTHREADS)
void matchnet_kernel(
    const float* __restrict__ X,
    const float* __restrict__ W1, const float* __restrict__ b1,
    const float* __restrict__ W2, const float* __restrict__ b2,
    const float* __restrict__ W3, const float* __restrict__ b3,
    const float* __restrict__ W4, const float* __restrict__ b4,
    float* __restrict__ out, int B)
{
    __shared__ float sW1[120], sW2[400], sW3[400], sW4[160];
    __shared__ float sb1[20], sb2[20], sb3[20], sb4[8];

    const int t = threadIdx.x;
    for (int i = t; i < 120; i += NTHREADS) sW1[i] = W1[i];
    for (int i = t; i < 400; i += NTHREADS) sW2[i] = W2[i];
    for (int i = t; i < 400; i += NTHREADS) sW3[i] = W3[i];
    for (int i = t; i < 160; i += NTHREADS) sW4[i] = W4[i];
    if (t < 20) { sb1[t] = b1[t]; sb2[t] = b2[t]; sb3[t] = b3[t]; }
    if (t < 8)  { sb4[t] = b4[t]; }
    __syncthreads();

    const int row = blockIdx.x * NTHREADS + t;
    if (row >= B) return;

    // ---- input row (RHS b of the LP), float2-vectorized ----
    float Z[6];
    {
        const float2* p = (const float2*)(X + row * 6);
        float2 a0 = p[0], a1 = p[1], a2 = p[2];
        Z[0] = a0.x; Z[1] = a0.y; Z[2] = a1.x;
        Z[3] = a1.y; Z[4] = a2.x; Z[5] = a2.y;
    }

    // ---- MLP ----
    float h1[20], h2[20];
#pragma unroll
    for (int j = 0; j < 20; j++) {
        float s = sb1[j];
#pragma unroll
        for (int k = 0; k < 6; k++) s = fmaf(Z[k], sW1[k * 20 + j], s);
        h1[j] = fast_tanh(s);
    }
#pragma unroll
    for (int j = 0; j < 20; j++) {
        float s = sb2[j];
#pragma unroll
        for (int k = 0; k < 20; k++) s = fmaf(h1[k], sW2[k * 20 + j], s);
        h2[j] = fast_tanh(s);
    }
#pragma unroll
    for (int j = 0; j < 20; j++) {
        float s = sb3[j];
#pragma unroll
        for (int k = 0; k < 20; k++) s = fmaf(h2[k], sW3[k * 20 + j], s);
        h1[j] = fast_tanh(s);   // reuse as h3
    }
    float z[8];
#pragma unroll
    for (int j = 0; j < 8; j++) {
        float s = sb4[j];
#pragma unroll
        for (int k = 0; k < 20; k++) s = fmaf(h1[k], sW4[k * 8 + j], s);
        z[j] = s;
    }

    // ---- PDHG (restructured) ----
    const float tau   = 0.18898223650461357f;   // 1/sqrt(28)
    const float sigma = tau;
    const float tc    = tau * 10.0f;

    // Per-row constants.
    // Sz_i = (S z)_i ; k_i = sigma*(Sz_i - Z_i) ; c3_j = sigma*z_j + sigma*tau
    float Sz[6];
    {
        float p02 = z[0] + z[2], p57 = z[5] + z[7], p13 = z[1] + z[3];
        float p01 = z[0] + z[1], p23 = z[2] + z[3], p12 = z[1] + z[2];
        float p47 = z[4] + z[7], p04 = z[0] + z[4];
        Sz[0] = p02 + p57; Sz[1] = p13 + z[4]; Sz[2] = p01 + z[6];
        Sz[3] = p23 + z[5]; Sz[4] = p12 + p47; Sz[5] = p04 + z[6];
    }
    float kc[6];
#pragma unroll
    for (int i = 0; i < 6; i++) kc[i] = sigma * (Sz[i] - Z[i]);
    float c3[8];
#pragma unroll
    for (int j = 0; j < 8; j++) c3[j] = fmaf(sigma, z[j], sigma * tau);

    // State init: x0 = max(z,0); sd0 = x0 - z; sdt = sd0 + tau; Ssd = S sd0.
    // Prologue dual update with xbar0 = x0: yI = max(0,-sigma*x0) = 0,
    // y6 = max(0, sigma*(S x0 - Z)) = max(0, fma(sigma, Ssd0, kc)).
    float sdt[8], yI[8], y6[6], Ssd[6];
    {
        float sd0[8];
#pragma unroll
        for (int j = 0; j < 8; j++) {
            sd0[j] = fmaxf(z[j], 0.0f) - z[j];
            sdt[j] = sd0[j] + tau;
            yI[j]  = 0.0f;
        }
        float p02 = sd0[0] + sd0[2], p57 = sd0[5] + sd0[7], p13 = sd0[1] + sd0[3];
        float p01 = sd0[0] + sd0[1], p23 = sd0[2] + sd0[3], p12 = sd0[1] + sd0[2];
        float p47 = sd0[4] + sd0[7], p04 = sd0[0] + sd0[4];
        Ssd[0] = p02 + p57; Ssd[1] = p13 + sd0[4]; Ssd[2] = p01 + sd0[6];
        Ssd[3] = p23 + sd0[5]; Ssd[4] = p12 + p47; Ssd[5] = p04 + sd0[6];
#pragma unroll
        for (int i = 0; i < 6; i++)
            y6[i] = fmaxf(0.0f, fmaf(sigma, Ssd[i], kc[i]));
    }

#pragma unroll 1
    for (int it = 0; it < 150; it++) {
        // ---- g = S^T y6 - yI (CSE'd) ----
        float q25 = y6[2] + y6[5], q04 = y6[0] + y6[4], q14 = y6[1] + y6[4];
        float g0 = (y6[0] + q25) - yI[0];
        float g1 = (q14 + y6[2]) - yI[1];
        float g2 = (q04 + y6[3]) - yI[2];
        float g3 = (y6[1] + y6[3]) - yI[3];
        float g4 = (q14 + y6[5]) - yI[4];
        float g5 = (y6[0] + y6[3]) - yI[5];
        float g6 = q25 - yI[6];
        float g7 = q04 - yI[7];

        // ---- d = fma(-tau, g, sdt) ; nn = ||d||^2 ----
        float d0 = fmaf(-tau, g0, sdt[0]);
        float d1 = fmaf(-tau, g1, sdt[1]);
        float d2 = fmaf(-tau, g2, sdt[2]);
        float d3 = fmaf(-tau, g3, sdt[3]);
        float d4 = fmaf(-tau, g4, sdt[4]);
        float d5 = fmaf(-tau, g5, sdt[5]);
        float d6 = fmaf(-tau, g6, sdt[6]);
        float d7 = fmaf(-tau, g7, sdt[7]);
        float p0 = fmaf(d0, d0, d1 * d1);
        float p1 = fmaf(d2, d2, d3 * d3);
        float p2 = fmaf(d4, d4, d5 * d5);
        float p3 = fmaf(d6, d6, d7 * d7);
        float nn = (p0 + p1) + (p2 + p3);
        float rr = fast_rsqrt(fmaxf(nn, 1e-24f));

        // ---- issued in the rsqrt shadow: S*d gather + pre-scale dual halves
        float e02 = d0 + d2, e57 = d5 + d7, e13 = d1 + d3;
        float e01 = d0 + d1, e23 = d2 + d3, e12 = d1 + d2;
        float e47 = d4 + d7, e04 = d0 + d4;
        float Sd0 = e02 + e57, Sd1 = e13 + d4, Sd2 = e01 + d6;
        float Sd3 = e23 + d5, Sd4 = e12 + e47, Sd5 = e04 + d6;

        // t1_j = yI_j - sigma*(z_j + tau) + sigma*sdt_j  (pre-scale yI half)
        float t1[8];
#pragma unroll
        for (int j = 0; j < 8; j++)
            t1[j] = fmaf(sigma, sdt[j], yI[j] - c3[j]);
        // t2_i = (y6_i + k_i) - sigma*Ssd_i              (pre-scale y6 half)
        float t2[6];
#pragma unroll
        for (int i = 0; i < 6; i++)
            t2[i] = fmaf(-sigma, Ssd[i], y6[i] + kc[i]);

        // ---- scale ----
        float scale = fmaxf(0.0f, fmaf(-tc, rr, 1.0f));
        float c2 = (2.0f * sigma) * scale;

        // ---- post-scale updates ----
        // y6 = max(0, t2 + c2*Sd) ; Ssd = scale*Sd
        y6[0] = fmaxf(0.0f, fmaf(c2, Sd0, t2[0])); Ssd[0] = scale * Sd0;
        y6[1] = fmaxf(0.0f, fmaf(c2, Sd1, t2[1])); Ssd[1] = scale * Sd1;
        y6[2] = fmaxf(0.0f, fmaf(c2, Sd2, t2[2])); Ssd[2] = scale * Sd2;
        y6[3] = fmaxf(0.0f, fmaf(c2, Sd3, t2[3])); Ssd[3] = scale * Sd3;
        y6[4] = fmaxf(0.0f, fmaf(c2, Sd4, t2[4])); Ssd[4] = scale * Sd4;
        y6[5] = fmaxf(0.0f, fmaf(c2, Sd5, t2[5])); Ssd[5] = scale * Sd5;
        // yI = max(0, t1 - c2*d) ; sdt = scale*d + tau
        yI[0] = fmaxf(0.0f, fmaf(-c2, d0, t1[0])); sdt[0] = fmaf(scale, d0, tau);
        yI[1] = fmaxf(0.0f, fmaf(-c2, d1, t1[1])); sdt[1] = fmaf(scale, d1, tau);
        yI[2] = fmaxf(0.0f, fmaf(-c2, d2, t1[2])); sdt[2] = fmaf(scale, d2, tau);
        yI[3] = fmaxf(0.0f, fmaf(-c2, d3, t1[3])); sdt[3] = fmaf(scale, d3, tau);
        yI[4] = fmaxf(0.0f, fmaf(-c2, d4, t1[4])); sdt[4] = fmaf(scale, d4, tau);
        yI[5] = fmaxf(0.0f, fmaf(-c2, d5, t1[5])); sdt[5] = fmaf(scale, d5, tau);
        yI[6] = fmaxf(0.0f, fmaf(-c2, d6, t1[6])); sdt[6] = fmaf(scale, d6, tau);
        yI[7] = fmaxf(0.0f, fmaf(-c2, d7, t1[7])); sdt[7] = fmaf(scale, d7, tau);
    }

    // ---- x = z + (sdt - tau); float4-vectorized store ----
    float xo[8];
#pragma unroll
    for (int j = 0; j < 8; j++) xo[j] = z[j] + (sdt[j] - tau);
    float4* p = (float4*)(out + row * 8);
    p[0] = make_float4(xo[0], xo[1], xo[2], xo[3]);
    p[1] = make_float4(xo[4], xo[5], xo[6], xo[7]);
}

extern "C" void kernel_launch(void* const* d_in, const int* in_sizes, int n_in,
                              void* d_out, int out_size) {
    const float* X  = (const float*)d_in[0];
    const float* W1 = (const float*)d_in[1];
    const float* b1 = (const float*)d_in[2];
    const float* W2 = (const float*)d_in[3];
    const float* b2 = (const float*)d_in[4];
    const float* W3 = (const float*)d_in[5];
    const float* b3 = (const float*)d_in[6];
    const float* W4 = (const float*)d_in[7];
    const float* b4 = (const float*)d_in[8];

    const int B = in_sizes[0] / 6;
    const int grid = (B + NTHREADS - 1) / NTHREADS;
    matchnet_kernel<<<grid, NTHREADS>>>(X, W1, b1, W2, b2, W3, b3, W4, b4,
                                        (float*)d_out, B);
}

// round 6
// speedup vs baseline: 1.2095x; 1.0576x over previous
#include <cuda_runtime.h>

// MatchNet: per-row MLP(6->20->20->20->8, tanh) + 150-iter PDHG LP.
// R6: full 150 iterations (mandatory — 120 iters gave 11% drift), with the
// lane-parallel math packed into f32x2 (FFMA2/ADD2, one fma-pipe issue per
// 2 lanes). Cross-lane gathers / norm / fmax stay scalar; pack/unpack movs
// and FMNMX ride the idle alu pipe. fma-pipe rt=2 is the binding ceiling.

#define NTHREADS 32
#define PDHG_ITERS 150

typedef unsigned long long u64;

__device__ __forceinline__ u64 pk(float a, float b) {
    u64 r; asm("mov.b64 %0, {%1, %2};" : "=l"(r) : "f"(a), "f"(b)); return r;
}
__device__ __forceinline__ void upk(float& a, float& b, u64 p) {
    asm("mov.b64 {%0, %1}, %2;" : "=f"(a), "=f"(b) : "l"(p));
}
__device__ __forceinline__ u64 fma2(u64 a, u64 b, u64 c) {
    u64 d; asm("fma.rn.f32x2 %0, %1, %2, %3;" : "=l"(d) : "l"(a), "l"(b), "l"(c)); return d;
}
__device__ __forceinline__ u64 add2(u64 a, u64 b) {
    u64 d; asm("add.rn.f32x2 %0, %1, %2;" : "=l"(d) : "l"(a), "l"(b)); return d;
}

__device__ __forceinline__ float fast_rsqrt(float v) {
    float r; asm("rsqrt.approx.f32 %0, %1;" : "=f"(r) : "f"(v)); return r;
}
__device__ __forceinline__ float fast_tanh(float x) {
    float e = __expf(2.0f * x);
    return 1.0f - __fdividef(2.0f, e + 1.0f);
}

__global__ __launch_bounds__(NTHREADS)
void matchnet_kernel(
    const float* __restrict__ X,
    const float* __restrict__ W1, const float* __restrict__ b1,
    const float* __restrict__ W2, const float* __restrict__ b2,
    const float* __restrict__ W3, const float* __restrict__ b3,
    const float* __restrict__ W4, const float* __restrict__ b4,
    float* __restrict__ out, int B)
{
    // 16B-aligned so u64 (LDS.64) loads at even-float offsets are legal.
    __shared__ __align__(16) float sW1[120], sW2[400], sW3[400], sW4[160];
    __shared__ __align__(16) float sb1[20], sb2[20], sb3[20], sb4[8];

    const int t = threadIdx.x;
    for (int i = t; i < 120; i += NTHREADS) sW1[i] = W1[i];
    for (int i = t; i < 400; i += NTHREADS) sW2[i] = W2[i];
    for (int i = t; i < 400; i += NTHREADS) sW3[i] = W3[i];
    for (int i = t; i < 160; i += NTHREADS) sW4[i] = W4[i];
    if (t < 20) { sb1[t] = b1[t]; sb2[t] = b2[t]; sb3[t] = b3[t]; }
    if (t < 8)  { sb4[t] = b4[t]; }
    __syncthreads();

    const int row = blockIdx.x * NTHREADS + t;
    if (row >= B) return;

    // ---- input row (RHS b of the LP) ----
    float Z[6];
    {
        const float2* p = (const float2*)(X + row * 6);
        float2 a0 = p[0], a1 = p[1], a2 = p[2];
        Z[0] = a0.x; Z[1] = a0.y; Z[2] = a1.x;
        Z[3] = a1.y; Z[4] = a2.x; Z[5] = a2.y;
    }

    // ---- MLP, f32x2-packed over output-neuron pairs ----
    float h[20], h2[20];
    {   // layer 1: 6 -> 20
        u64 a[10];
#pragma unroll
        for (int jp = 0; jp < 10; jp++) a[jp] = *(const u64*)&sb1[2 * jp];
#pragma unroll
        for (int k = 0; k < 6; k++) {
            u64 zz = pk(Z[k], Z[k]);
#pragma unroll
            for (int jp = 0; jp < 10; jp++)
                a[jp] = fma2(zz, *(const u64*)&sW1[k * 20 + 2 * jp], a[jp]);
        }
#pragma unroll
        for (int jp = 0; jp < 10; jp++) {
            float s0, s1; upk(s0, s1, a[jp]);
            h[2 * jp] = fast_tanh(s0); h[2 * jp + 1] = fast_tanh(s1);
        }
    }
    {   // layer 2: 20 -> 20
        u64 a[10];
#pragma unroll
        for (int jp = 0; jp < 10; jp++) a[jp] = *(const u64*)&sb2[2 * jp];
#pragma unroll
        for (int k = 0; k < 20; k++) {
            u64 hh = pk(h[k], h[k]);
#pragma unroll
            for (int jp = 0; jp < 10; jp++)
                a[jp] = fma2(hh, *(const u64*)&sW2[k * 20 + 2 * jp], a[jp]);
        }
#pragma unroll
        for (int jp = 0; jp < 10; jp++) {
            float s0, s1; upk(s0, s1, a[jp]);
            h2[2 * jp] = fast_tanh(s0); h2[2 * jp + 1] = fast_tanh(s1);
        }
    }
    {   // layer 3: 20 -> 20 (back into h)
        u64 a[10];
#pragma unroll
        for (int jp = 0; jp < 10; jp++) a[jp] = *(const u64*)&sb3[2 * jp];
#pragma unroll
        for (int k = 0; k < 20; k++) {
            u64 hh = pk(h2[k], h2[k]);
#pragma unroll
            for (int jp = 0; jp < 10; jp++)
                a[jp] = fma2(hh, *(const u64*)&sW3[k * 20 + 2 * jp], a[jp]);
        }
#pragma unroll
        for (int jp = 0; jp < 10; jp++) {
            float s0, s1; upk(s0, s1, a[jp]);
            h[2 * jp] = fast_tanh(s0); h[2 * jp + 1] = fast_tanh(s1);
        }
    }
    float z[8];
    {   // layer 4: 20 -> 8 (no activation)
        u64 a[4];
#pragma unroll
        for (int jp = 0; jp < 4; jp++) a[jp] = *(const u64*)&sb4[2 * jp];
#pragma unroll
        for (int k = 0; k < 20; k++) {
            u64 hh = pk(h[k], h[k]);
#pragma unroll
            for (int jp = 0; jp < 4; jp++)
                a[jp] = fma2(hh, *(const u64*)&sW4[k * 8 + 2 * jp], a[jp]);
        }
#pragma unroll
        for (int jp = 0; jp < 4; jp++) upk(z[2 * jp], z[2 * jp + 1], a[jp]);
    }

    // ---- PDHG constants ----
    const float tau   = 0.18898223650461357f;   // 1/sqrt(28)
    const float sigma = tau;
    const float tc    = tau * 10.0f;

    // Sz, kc_i = sigma*(Sz_i - Z_i), c4_j = sigma*z_j
    float kc0, kc1, kc2, kc3, kc4, kc5;
    {
        float p02 = z[0] + z[2], p57 = z[5] + z[7], p13 = z[1] + z[3];
        float p01 = z[0] + z[1], p23 = z[2] + z[3], p12 = z[1] + z[2];
        float p47 = z[4] + z[7], p04 = z[0] + z[4];
        kc0 = sigma * ((p02 + p57) - Z[0]);
        kc1 = sigma * ((p13 + z[4]) - Z[1]);
        kc2 = sigma * ((p01 + z[6]) - Z[2]);
        kc3 = sigma * ((p23 + z[5]) - Z[3]);
        kc4 = sigma * ((p12 + p47) - Z[4]);
        kc5 = sigma * ((p04 + z[6]) - Z[5]);
    }
    const u64 kcp0 = pk(kc0, kc1), kcp1 = pk(kc2, kc3), kcp2 = pk(kc4, kc5);
    u64 negc4p[4];
#pragma unroll
    for (int jp = 0; jp < 4; jp++)
        negc4p[jp] = pk(-sigma * z[2 * jp], -sigma * z[2 * jp + 1]);
    const u64 ntau2 = pk(-tau, -tau);
    const u64 tau2  = pk(tau, tau);

    // ---- state init ----
    // x0 = max(z,0); sd0 = x0 - z; sdt = sd0 + tau; d_prev := sd0 (ss=sigma);
    // Sd_prev = S*sd0; prologue dual: yI = 0, y6 = max(0, sigma*Sd_prev + kc).
    float y0, y1, y2, y3, y4, y5;
    float yi0 = 0.f, yi1 = 0.f, yi2 = 0.f, yi3 = 0.f,
          yi4 = 0.f, yi5 = 0.f, yi6 = 0.f, yi7 = 0.f;
    u64 sdtp[4], dpp[4], SdPp[3];
    float ss = sigma, ssn = -sigma;
    {
        float sd[8];
#pragma unroll
        for (int j = 0; j < 8; j++) sd[j] = fmaxf(z[j], 0.0f) - z[j];
#pragma unroll
        for (int jp = 0; jp < 4; jp++) {
            dpp[jp]  = pk(sd[2 * jp], sd[2 * jp + 1]);
            sdtp[jp] = pk(sd[2 * jp] + tau, sd[2 * jp + 1] + tau);
        }
        float p02 = sd[0] + sd[2], p57 = sd[5] + sd[7], p13 = sd[1] + sd[3];
        float p01 = sd[0] + sd[1], p23 = sd[2] + sd[3], p12 = sd[1] + sd[2];
        float p47 = sd[4] + sd[7], p04 = sd[0] + sd[4];
        float S0 = p02 + p57, S1 = p13 + sd[4], S2 = p01 + sd[6];
        float S3 = p23 + sd[5], S4 = p12 + p47, S5 = p04 + sd[6];
        SdPp[0] = pk(S0, S1); SdPp[1] = pk(S2, S3); SdPp[2] = pk(S4, S5);
        y0 = fmaxf(0.0f, fmaf(sigma, S0, kc0));
        y1 = fmaxf(0.0f, fmaf(sigma, S1, kc1));
        y2 = fmaxf(0.0f, fmaf(sigma, S2, kc2));
        y3 = fmaxf(0.0f, fmaf(sigma, S3, kc3));
        y4 = fmaxf(0.0f, fmaf(sigma, S4, kc4));
        y5 = fmaxf(0.0f, fmaf(sigma, S5, kc5));
    }

#pragma unroll 1
    for (int it = 0; it < PDHG_ITERS; it++) {
        // ---- g = S^T y - yI (scalar gathers) ----
        float q25 = y2 + y5, q04 = y0 + y4, q14 = y1 + y4;
        float g0 = (y0 + q25) - yi0;
        float g1 = (q14 + y2) - yi1;
        float g2 = (q04 + y3) - yi2;
        float g3 = (y1 + y3) - yi3;
        float g4 = (q14 + y5) - yi4;
        float g5 = (y0 + y3) - yi5;
        float g6 = q25 - yi6;
        float g7 = q04 - yi7;

        // ---- d = fma2(-tau, g, sdt) ----
        u64 dk0 = fma2(ntau2, pk(g0, g1), sdtp[0]);
        u64 dk1 = fma2(ntau2, pk(g2, g3), sdtp[1]);
        u64 dk2 = fma2(ntau2, pk(g4, g5), sdtp[2]);
        u64 dk3 = fma2(ntau2, pk(g6, g7), sdtp[3]);
        float d0, d1, d2, d3, d4, d5, d6, d7;
        upk(d0, d1, dk0); upk(d2, d3, dk1);
        upk(d4, d5, dk2); upk(d6, d7, dk3);

        // ---- ||d||^2 tree + rsqrt ----
        float p0 = fmaf(d0, d0, d1 * d1);
        float p1 = fmaf(d2, d2, d3 * d3);
        float p2 = fmaf(d4, d4, d5 * d5);
        float p3 = fmaf(d6, d6, d7 * d7);
        float nn = (p0 + p1) + (p2 + p3);
        float rr = fast_rsqrt(fmaxf(nn, 1e-24f));

        // ---- S*d gather (scalar) ----
        float e02 = d0 + d2, e57 = d5 + d7, e13 = d1 + d3;
        float e01 = d0 + d1, e23 = d2 + d3, e12 = d1 + d2;
        float e47 = d4 + d7, e04 = d0 + d4;
        float Sd0 = e02 + e57, Sd1 = e13 + d4, Sd2 = e01 + d6;
        float Sd3 = e23 + d5, Sd4 = e12 + e47, Sd5 = e04 + d6;

        // ---- pre-scale dual halves (packed) ----
        // t1 = yI - sigma*z + ss*d_prev ; t2 = (y + kc) - ss*Sd_prev
        u64 ss2  = pk(ss, ss);
        u64 ssn2 = pk(ssn, ssn);
        u64 t10 = fma2(ss2, dpp[0], add2(pk(yi0, yi1), negc4p[0]));
        u64 t11 = fma2(ss2, dpp[1], add2(pk(yi2, yi3), negc4p[1]));
        u64 t12 = fma2(ss2, dpp[2], add2(pk(yi4, yi5), negc4p[2]));
        u64 t13 = fma2(ss2, dpp[3], add2(pk(yi6, yi7), negc4p[3]));
        u64 t20 = fma2(ssn2, SdPp[0], add2(pk(y0, y1), kcp0));
        u64 t21 = fma2(ssn2, SdPp[1], add2(pk(y2, y3), kcp1));
        u64 t22 = fma2(ssn2, SdPp[2], add2(pk(y4, y5), kcp2));

        // ---- scale ----
        float scale = fmaxf(0.0f, fmaf(-tc, rr, 1.0f));
        float c2  = (2.0f * sigma) * scale;
        float nc2 = -c2;
        ss  = sigma * scale;
        ssn = -ss;
        u64 c22  = pk(c2, c2);
        u64 nc22 = pk(nc2, nc2);
        u64 sc2  = pk(scale, scale);

        // ---- post-scale updates ----
        // y = max(0, t2 + c2*Sd)
        {
            float a, b;
            u64 yn0 = fma2(c22, pk(Sd0, Sd1), t20);
            u64 yn1 = fma2(c22, pk(Sd2, Sd3), t21);
            u64 yn2 = fma2(c22, pk(Sd4, Sd5), t22);
            upk(a, b, yn0); y0 = fmaxf(0.0f, a); y1 = fmaxf(0.0f, b);
            upk(a, b, yn1); y2 = fmaxf(0.0f, a); y3 = fmaxf(0.0f, b);
            upk(a, b, yn2); y4 = fmaxf(0.0f, a); y5 = fmaxf(0.0f, b);
        }
        // yI = max(0, t1 - c2*d)
        {
            float a, b;
            u64 yn0 = fma2(nc22, dk0, t10);
            u64 yn1 = fma2(nc22, dk1, t11);
            u64 yn2 = fma2(nc22, dk2, t12);
            u64 yn3 = fma2(nc22, dk3, t13);
            upk(a, b, yn0); yi0 = fmaxf(0.0f, a); yi1 = fmaxf(0.0f, b);
            upk(a, b, yn1); yi2 = fmaxf(0.0f, a); yi3 = fmaxf(0.0f, b);
            upk(a, b, yn2); yi4 = fmaxf(0.0f, a); yi5 = fmaxf(0.0f, b);
            upk(a, b, yn3); yi6 = fmaxf(0.0f, a); yi7 = fmaxf(0.0f, b);
        }
        // sdt = scale*d + tau ; carry d_prev, Sd_prev (raw)
        sdtp[0] = fma2(sc2, dk0, tau2);
        sdtp[1] = fma2(sc2, dk1, tau2);
        sdtp[2] = fma2(sc2, dk2, tau2);
        sdtp[3] = fma2(sc2, dk3, tau2);
        dpp[0] = dk0; dpp[1] = dk1; dpp[2] = dk2; dpp[3] = dk3;
        SdPp[0] = pk(Sd0, Sd1); SdPp[1] = pk(Sd2, Sd3); SdPp[2] = pk(Sd4, Sd5);
    }

    // ---- x = z + (sdt - tau); float4-vectorized store ----
    float xo[8];
#pragma unroll
    for (int jp = 0; jp < 4; jp++) {
        float a, b; upk(a, b, sdtp[jp]);
        xo[2 * jp]     = z[2 * jp]     + (a - tau);
        xo[2 * jp + 1] = z[2 * jp + 1] + (b - tau);
    }
    float4* p = (float4*)(out + row * 8);
    p[0] = make_float4(xo[0], xo[1], xo[2], xo[3]);
    p[1] = make_float4(xo[4], xo[5], xo[6], xo[7]);
}

extern "C" void kernel_launch(void* const* d_in, const int* in_sizes, int n_in,
                              void* d_out, int out_size) {
    const float* X  = (const float*)d_in[0];
    const float* W1 = (const float*)d_in[1];
    const float* b1 = (const float*)d_in[2];
    const float* W2 = (const float*)d_in[3];
    const float* b2 = (const float*)d_in[4];
    const float* W3 = (const float*)d_in[5];
    const float* b3 = (const float*)d_in[6];
    const float* W4 = (const float*)d_in[7];
    const float* b4 = (const float*)d_in[8];

    const int B = in_sizes[0] / 6;
    const int grid = (B + NTHREADS - 1) / NTHREADS;
    matchnet_kernel<<<grid, NTHREADS>>>(X, W1, b1, W2, b2, W3, b3, W4, b4,
                                        (float*)d_out, B);
}

// round 7
// speedup vs baseline: 1.2194x; 1.0082x over previous
#include <cuda_runtime.h>

// MatchNet: per-row MLP(6->20->20->20->8, tanh) + 150-iter PDHG LP.
// R7: chain-minimal scalar PDHG. e-carry (e = sdt + tau*yI) removes yI from
// the head; no eps clamp before rsqrt (rr=inf -> scale=0 is exact); c2/ss/
// scale each one fma+fmax straight off rr; negations via FFMA modifiers;
// unroll 2. MLP stays f32x2-packed (off-chain).

#define NTHREADS 32
#define PDHG_ITERS 150

typedef unsigned long long u64;

__device__ __forceinline__ u64 pk(float a, float b) {
    u64 r; asm("mov.b64 %0, {%1, %2};" : "=l"(r) : "f"(a), "f"(b)); return r;
}
__device__ __forceinline__ void upk(float& a, float& b, u64 p) {
    asm("mov.b64 {%0, %1}, %2;" : "=f"(a), "=f"(b) : "l"(p));
}
__device__ __forceinline__ u64 fma2(u64 a, u64 b, u64 c) {
    u64 d; asm("fma.rn.f32x2 %0, %1, %2, %3;" : "=l"(d) : "l"(a), "l"(b), "l"(c)); return d;
}

__device__ __forceinline__ float fast_rsqrt(float v) {
    float r; asm("rsqrt.approx.f32 %0, %1;" : "=f"(r) : "f"(v)); return r;
}
__device__ __forceinline__ float fast_tanh(float x) {
    float e = __expf(2.0f * x);
    return 1.0f - __fdividef(2.0f, e + 1.0f);
}

__global__ __launch_bounds__(NTHREADS)
void matchnet_kernel(
    const float* __restrict__ X,
    const float* __restrict__ W1, const float* __restrict__ b1,
    const float* __restrict__ W2, const float* __restrict__ b2,
    const float* __restrict__ W3, const float* __restrict__ b3,
    const float* __restrict__ W4, const float* __restrict__ b4,
    float* __restrict__ out, int B)
{
    __shared__ __align__(16) float sW1[120], sW2[400], sW3[400], sW4[160];
    __shared__ __align__(16) float sb1[20], sb2[20], sb3[20], sb4[8];

    const int t = threadIdx.x;
    for (int i = t; i < 120; i += NTHREADS) sW1[i] = W1[i];
    for (int i = t; i < 400; i += NTHREADS) sW2[i] = W2[i];
    for (int i = t; i < 400; i += NTHREADS) sW3[i] = W3[i];
    for (int i = t; i < 160; i += NTHREADS) sW4[i] = W4[i];
    if (t < 20) { sb1[t] = b1[t]; sb2[t] = b2[t]; sb3[t] = b3[t]; }
    if (t < 8)  { sb4[t] = b4[t]; }
    __syncthreads();

    const int row = blockIdx.x * NTHREADS + t;
    if (row >= B) return;

    // ---- input row (RHS b of the LP) ----
    float Z[6];
    {
        const float2* p = (const float2*)(X + row * 6);
        float2 a0 = p[0], a1 = p[1], a2 = p[2];
        Z[0] = a0.x; Z[1] = a0.y; Z[2] = a1.x;
        Z[3] = a1.y; Z[4] = a2.x; Z[5] = a2.y;
    }

    // ---- MLP, f32x2-packed over output-neuron pairs (validated R6) ----
    float h[20], h2[20];
    {   // layer 1: 6 -> 20
        u64 a[10];
#pragma unroll
        for (int jp = 0; jp < 10; jp++) a[jp] = *(const u64*)&sb1[2 * jp];
#pragma unroll
        for (int k = 0; k < 6; k++) {
            u64 zz = pk(Z[k], Z[k]);
#pragma unroll
            for (int jp = 0; jp < 10; jp++)
                a[jp] = fma2(zz, *(const u64*)&sW1[k * 20 + 2 * jp], a[jp]);
        }
#pragma unroll
        for (int jp = 0; jp < 10; jp++) {
            float s0, s1; upk(s0, s1, a[jp]);
            h[2 * jp] = fast_tanh(s0); h[2 * jp + 1] = fast_tanh(s1);
        }
    }
    {   // layer 2: 20 -> 20
        u64 a[10];
#pragma unroll
        for (int jp = 0; jp < 10; jp++) a[jp] = *(const u64*)&sb2[2 * jp];
#pragma unroll
        for (int k = 0; k < 20; k++) {
            u64 hh = pk(h[k], h[k]);
#pragma unroll
            for (int jp = 0; jp < 10; jp++)
                a[jp] = fma2(hh, *(const u64*)&sW2[k * 20 + 2 * jp], a[jp]);
        }
#pragma unroll
        for (int jp = 0; jp < 10; jp++) {
            float s0, s1; upk(s0, s1, a[jp]);
            h2[2 * jp] = fast_tanh(s0); h2[2 * jp + 1] = fast_tanh(s1);
        }
    }
    {   // layer 3: 20 -> 20 (back into h)
        u64 a[10];
#pragma unroll
        for (int jp = 0; jp < 10; jp++) a[jp] = *(const u64*)&sb3[2 * jp];
#pragma unroll
        for (int k = 0; k < 20; k++) {
            u64 hh = pk(h2[k], h2[k]);
#pragma unroll
            for (int jp = 0; jp < 10; jp++)
                a[jp] = fma2(hh, *(const u64*)&sW3[k * 20 + 2 * jp], a[jp]);
        }
#pragma unroll
        for (int jp = 0; jp < 10; jp++) {
            float s0, s1; upk(s0, s1, a[jp]);
            h[2 * jp] = fast_tanh(s0); h[2 * jp + 1] = fast_tanh(s1);
        }
    }
    float z[8];
    {   // layer 4: 20 -> 8
        u64 a[4];
#pragma unroll
        for (int jp = 0; jp < 4; jp++) a[jp] = *(const u64*)&sb4[2 * jp];
#pragma unroll
        for (int k = 0; k < 20; k++) {
            u64 hh = pk(h[k], h[k]);
#pragma unroll
            for (int jp = 0; jp < 4; jp++)
                a[jp] = fma2(hh, *(const u64*)&sW4[k * 8 + 2 * jp], a[jp]);
        }
#pragma unroll
        for (int jp = 0; jp < 4; jp++) upk(z[2 * jp], z[2 * jp + 1], a[jp]);
    }

    // ---- PDHG constants ----
    const float tau   = 0.18898223650461357f;   // 1/sqrt(28)
    const float sigma = tau;
    const float tc    = tau * 10.0f;            // tau*control_strength
    const float twoSigma = 2.0f * sigma;
    const float tc1   = tc;                      // for scale
    const float tc2s  = twoSigma * tc;           // for c2
    const float tcs   = sigma * tc;              // for ss

    // kc_i = sigma*(Sz_i - Z_i), nc4_j = -sigma*z_j
    float kc[6];
    {
        float p02 = z[0] + z[2], p57 = z[5] + z[7], p13 = z[1] + z[3];
        float p01 = z[0] + z[1], p23 = z[2] + z[3], p12 = z[1] + z[2];
        float p47 = z[4] + z[7], p04 = z[0] + z[4];
        kc[0] = sigma * ((p02 + p57) - Z[0]);
        kc[1] = sigma * ((p13 + z[4]) - Z[1]);
        kc[2] = sigma * ((p01 + z[6]) - Z[2]);
        kc[3] = sigma * ((p23 + z[5]) - Z[3]);
        kc[4] = sigma * ((p12 + p47) - Z[4]);
        kc[5] = sigma * ((p04 + z[6]) - Z[5]);
    }
    float nc4[8];
#pragma unroll
    for (int j = 0; j < 8; j++) nc4[j] = -sigma * z[j];

    // ---- state init (matches validated R4/R6 prologue) ----
    // x0 = max(z,0); sd0 = x0 - z; dp = sd0 (ss = sigma); SdP = S*sd0;
    // yI = 0; y6 = max(0, sigma*SdP + kc); e = sd0 + tau  (yI=0).
    float e[8], dp[8], SdP[6], y[6], yi[8];
    float ss = sigma;
    {
        float sd[8];
#pragma unroll
        for (int j = 0; j < 8; j++) {
            sd[j] = fmaxf(z[j], 0.0f) - z[j];
            dp[j] = sd[j];
            e[j]  = sd[j] + tau;
            yi[j] = 0.0f;
        }
        float p02 = sd[0] + sd[2], p57 = sd[5] + sd[7], p13 = sd[1] + sd[3];
        float p01 = sd[0] + sd[1], p23 = sd[2] + sd[3], p12 = sd[1] + sd[2];
        float p47 = sd[4] + sd[7], p04 = sd[0] + sd[4];
        SdP[0] = p02 + p57; SdP[1] = p13 + sd[4]; SdP[2] = p01 + sd[6];
        SdP[3] = p23 + sd[5]; SdP[4] = p12 + p47; SdP[5] = p04 + sd[6];
#pragma unroll
        for (int i = 0; i < 6; i++)
            y[i] = fmaxf(0.0f, fmaf(sigma, SdP[i], kc[i]));
    }

#pragma unroll 2
    for (int it = 0; it < PDHG_ITERS; it++) {
        // ---- HEAD (loop-carried chain): y -> sy -> d -> nn -> rr ----
        float q25 = y[2] + y[5], q04 = y[0] + y[4], q14 = y[1] + y[4];
        float sy0 = y[0] + q25;
        float sy1 = q14 + y[2];
        float sy2 = q04 + y[3];
        float sy3 = y[1] + y[3];
        float sy4 = q14 + y[5];
        float sy5 = y[0] + y[3];
        // sy6 = q25, sy7 = q04

        float d0 = fmaf(-tau, sy0, e[0]);
        float d1 = fmaf(-tau, sy1, e[1]);
        float d2 = fmaf(-tau, sy2, e[2]);
        float d3 = fmaf(-tau, sy3, e[3]);
        float d4 = fmaf(-tau, sy4, e[4]);
        float d5 = fmaf(-tau, sy5, e[5]);
        float d6 = fmaf(-tau, q25, e[6]);
        float d7 = fmaf(-tau, q04, e[7]);

        float p0 = fmaf(d0, d0, d1 * d1);
        float p1 = fmaf(d2, d2, d3 * d3);
        float p2 = fmaf(d4, d4, d5 * d5);
        float p3 = fmaf(d6, d6, d7 * d7);
        float nn = (p0 + p1) + (p2 + p3);
        float rr = fast_rsqrt(nn);   // nn=0 -> rr=inf -> scale=0 (exact)

        // ---- SHADOW (independent of rr) ----
        float f02 = d0 + d2, f57 = d5 + d7, f13 = d1 + d3;
        float f01 = d0 + d1, f23 = d2 + d3, f12 = d1 + d2;
        float f47 = d4 + d7, f04 = d0 + d4;
        float Sd0 = f02 + f57, Sd1 = f13 + d4, Sd2 = f01 + d6;
        float Sd3 = f23 + d5, Sd4 = f12 + f47, Sd5 = f04 + d6;

        // t1_j = (yi_j - sigma*z_j) + ss*dp_j
        float t1[8];
#pragma unroll
        for (int j = 0; j < 8; j++)
            t1[j] = fmaf(ss, dp[j], yi[j] + nc4[j]);
        // t2_i = (y_i + kc_i) - ss*SdP_i
        float t2[6];
#pragma unroll
        for (int i = 0; i < 6; i++)
            t2[i] = fmaf(-ss, SdP[i], y[i] + kc[i]);

        // ---- scale family (each one fma+fmax off rr) ----
        float scale = fmaxf(0.0f, fmaf(-tc1,  rr, 1.0f));
        float c2    = fmaxf(0.0f, fmaf(-tc2s, rr, twoSigma));
        ss          = fmaxf(0.0f, fmaf(-tcs,  rr, sigma));

        // ---- TAIL ----
        y[0] = fmaxf(0.0f, fmaf(c2, Sd0, t2[0]));
        y[1] = fmaxf(0.0f, fmaf(c2, Sd1, t2[1]));
        y[2] = fmaxf(0.0f, fmaf(c2, Sd2, t2[2]));
        y[3] = fmaxf(0.0f, fmaf(c2, Sd3, t2[3]));
        y[4] = fmaxf(0.0f, fmaf(c2, Sd4, t2[4]));
        y[5] = fmaxf(0.0f, fmaf(c2, Sd5, t2[5]));

        yi[0] = fmaxf(0.0f, fmaf(-c2, d0, t1[0]));
        yi[1] = fmaxf(0.0f, fmaf(-c2, d1, t1[1]));
        yi[2] = fmaxf(0.0f, fmaf(-c2, d2, t1[2]));
        yi[3] = fmaxf(0.0f, fmaf(-c2, d3, t1[3]));
        yi[4] = fmaxf(0.0f, fmaf(-c2, d4, t1[4]));
        yi[5] = fmaxf(0.0f, fmaf(-c2, d5, t1[5]));
        yi[6] = fmaxf(0.0f, fmaf(-c2, d6, t1[6]));
        yi[7] = fmaxf(0.0f, fmaf(-c2, d7, t1[7]));

        // sdt = scale*d + tau ; e = sdt + tau*yi (next-iter head input)
        e[0] = fmaf(tau, yi[0], fmaf(scale, d0, tau));
        e[1] = fmaf(tau, yi[1], fmaf(scale, d1, tau));
        e[2] = fmaf(tau, yi[2], fmaf(scale, d2, tau));
        e[3] = fmaf(tau, yi[3], fmaf(scale, d3, tau));
        e[4] = fmaf(tau, yi[4], fmaf(scale, d4, tau));
        e[5] = fmaf(tau, yi[5], fmaf(scale, d5, tau));
        e[6] = fmaf(tau, yi[6], fmaf(scale, d6, tau));
        e[7] = fmaf(tau, yi[7], fmaf(scale, d7, tau));

        dp[0] = d0; dp[1] = d1; dp[2] = d2; dp[3] = d3;
        dp[4] = d4; dp[5] = d5; dp[6] = d6; dp[7] = d7;
        SdP[0] = Sd0; SdP[1] = Sd1; SdP[2] = Sd2;
        SdP[3] = Sd3; SdP[4] = Sd4; SdP[5] = Sd5;
    }

    // ---- x = z + sd; sd = sdt - tau = (e - tau*yi) - tau ----
    float xo[8];
#pragma unroll
    for (int j = 0; j < 8; j++)
        xo[j] = z[j] + (fmaf(-tau, yi[j], e[j]) - tau);
    float4* p = (float4*)(out + row * 8);
    p[0] = make_float4(xo[0], xo[1], xo[2], xo[3]);
    p[1] = make_float4(xo[4], xo[5], xo[6], xo[7]);
}

extern "C" void kernel_launch(void* const* d_in, const int* in_sizes, int n_in,
                              void* d_out, int out_size) {
    const float* X  = (const float*)d_in[0];
    const float* W1 = (const float*)d_in[1];
    const float* b1 = (const float*)d_in[2];
    const float* W2 = (const float*)d_in[3];
    const float* b2 = (const float*)d_in[4];
    const float* W3 = (const float*)d_in[5];
    const float* b3 = (const float*)d_in[6];
    const float* W4 = (const float*)d_in[7];
    const float* b4 = (const float*)d_in[8];

    const int B = in_sizes[0] / 6;
    const int grid = (B + NTHREADS - 1) / NTHREADS;
    matchnet_kernel<<<grid, NTHREADS>>>(X, W1, b1, W2, b2, W3, b3, W4, b4,
                                        (float*)d_out, B);
}